// round 5
// baseline (speedup 1.0000x reference)
#include <cuda_runtime.h>
#include <cstdint>

// ---------------------------------------------------------------------------
// Border-ownership / grouping network, fused.
//   Stage A (border_kernel): 2x conv(1->8, 11x11) + spike + WTA logic
//                            -> 16 channels in {0,1,2}, packed 2b each -> u32
//   Stage B (group_kernel):  depthwise 23x23 conv per (batch, orientation)
//                            (4 channels each) + spike + combine -> u8 partial
//   Stage C (combine):       sum 4 orientation partials -> fp32 out
// ---------------------------------------------------------------------------

static constexpr int IMG  = 512;
static constexpr int NPIX = IMG * IMG;
static constexpr int NB   = 4;

__device__ uint32_t      g_border[(size_t)NB * NPIX];        // packed 16x2-bit
__device__ unsigned char g_partial[(size_t)NB * 4 * NPIX];   // per (b, ori)

// ---------------------------- Stage A --------------------------------------
static constexpr int TA = 32;          // output tile
static constexpr int HA = TA + 10;     // 42 (halo 5 each side)
static constexpr int PA = 44;          // padded row (mult of 4)
static constexpr int SA = HA * PA;     // per-channel plane (floats)

__global__ __launch_bounds__(256)
void border_kernel(const float* __restrict__ inp, const float* __restrict__ Wb)
{
    __shared__ __align__(16) float sIn[2 * SA];        // 14.8 KB
    __shared__ __align__(16) float sW[8 * 11 * 12];    // 4.2 KB

    const int b   = blockIdx.z;
    const int x0  = blockIdx.x * TA;
    const int y0  = blockIdx.y * TA;
    const int tid = threadIdx.x;

    // Load 2-channel input tile with halo (zero pad outside image)
    for (int idx = tid; idx < 2 * HA * HA; idx += 256) {
        int ch  = idx / (HA * HA);
        int rem = idx - ch * HA * HA;
        int r = rem / HA, c = rem - r * HA;
        int gy = y0 - 5 + r, gx = x0 - 5 + c;
        float v = 0.f;
        if ((unsigned)gy < IMG && (unsigned)gx < IMG)
            v = inp[(((size_t)b * 2 + ch) * IMG + gy) * IMG + gx];
        sIn[ch * SA + r * PA + c] = v;
    }
    // Load border weights (8 filters, 11x11), rows padded to 12
    for (int idx = tid; idx < 8 * 121; idx += 256) {
        int f   = idx / 121;
        int rem = idx - f * 121;
        int r = rem / 11, c = rem - r * 11;
        sW[(f * 11 + r) * 12 + c] = Wb[idx];
    }
    __syncthreads();

    const int tx  = tid & 7, ty = tid >> 3;
    const int x0l = tx * 4;                 // 4 output pixels per thread (x)

    float vm[4];
#pragma unroll
    for (int p = 0; p < 4; p++)
        vm[p] = sIn[(ty + 5) * PA + x0l + 5 + p]
              + sIn[SA + (ty + 5) * PA + x0l + 5 + p];

    unsigned pb[4] = {0, 0, 0, 0};   // pos spike bits per pixel (8 filters)
    unsigned nb[4] = {0, 0, 0, 0};   // neg spike bits

#pragma unroll 1
    for (int f = 0; f < 8; f++) {
        float aP[4] = {0.f, 0.f, 0.f, 0.f};
        float aN[4] = {0.f, 0.f, 0.f, 0.f};
#pragma unroll 1
        for (int ky = 0; ky < 11; ky++) {
            float w[12], i0[16], i1[16];
            {
                const float4* s = (const float4*)&sW[(f * 11 + ky) * 12];
#pragma unroll
                for (int i = 0; i < 3; i++) {
                    float4 v = s[i];
                    w[4*i] = v.x; w[4*i+1] = v.y; w[4*i+2] = v.z; w[4*i+3] = v.w;
                }
            }
            {
                const float4* s = (const float4*)&sIn[(ty + ky) * PA + x0l];
#pragma unroll
                for (int i = 0; i < 4; i++) {
                    float4 v = s[i];
                    i0[4*i] = v.x; i0[4*i+1] = v.y; i0[4*i+2] = v.z; i0[4*i+3] = v.w;
                }
            }
            {
                const float4* s = (const float4*)&sIn[SA + (ty + ky) * PA + x0l];
#pragma unroll
                for (int i = 0; i < 4; i++) {
                    float4 v = s[i];
                    i1[4*i] = v.x; i1[4*i+1] = v.y; i1[4*i+2] = v.z; i1[4*i+3] = v.w;
                }
            }
#pragma unroll
            for (int kx = 0; kx < 11; kx++) {
                float wv = w[kx];
#pragma unroll
                for (int p = 0; p < 4; p++) {
                    aP[p] += i0[kx + p] * wv;
                    aN[p] += i1[kx + p] * wv;
                }
            }
        }
#pragma unroll
        for (int p = 0; p < 4; p++) {
            if (aP[p] >= 1.f) pb[p] |= 1u << f;
            if (aN[p] >= 1.f) nb[p] |= 1u << f;
        }
    }

    // Per-pixel border logic: B_INH=1.5, G_INH=1.0
#pragma unroll
    for (int p = 0; p < 4; p++) {
        const float v = vm[p];
        int b13[4], b24[4];
#pragma unroll
        for (int o = 0; o < 4; o++) {
            float pe  = (float)((pb[p] >> (2 * o))     & 1u);
            float po  = (float)((pb[p] >> (2 * o + 1)) & 1u);
            float ne  = (float)((nb[p] >> (2 * o))     & 1u);
            float no_ = (float)((nb[p] >> (2 * o + 1)) & 1u);
            b13[o] = (v * (pe  - 1.5f * no_) >= 1.f ? 1 : 0)
                   + (v * (ne  - 1.5f * po ) >= 1.f ? 1 : 0);
            b24[o] = (v * (po  - 1.5f * ne ) >= 1.f ? 1 : 0)
                   + (v * (no_ - 1.5f * pe ) >= 1.f ? 1 : 0);
        }
        int m = 0;
#pragma unroll
        for (int o = 0; o < 4; o++) {
            int d = b13[o] - b24[o];
            int t = d < 0 ? -d : d;
            m = t > m ? t : m;
        }
        uint32_t pk = 0;
#pragma unroll
        for (int o = 0; o < 4; o++) {
            int d   = b13[o] - b24[o];
            int t   = d < 0 ? -d : d;
            int wta = (t == m);
            int b1p = wta && (d >= 1);
            int b1n = wta && (d <= -1);
            int c0 = b1p ? b13[o] : 0;
            int c1 = b1p ? b24[o] : 0;
            int c2 = b1n ? b24[o] : 0;
            int c3 = b1n ? b13[o] : 0;
            pk |= (uint32_t)(c0 | (c1 << 2) | (c2 << 4) | (c3 << 6)) << (8 * o);
        }
        g_border[((size_t)b * IMG + (y0 + ty)) * IMG + (x0 + x0l + p)] = pk;
    }
}

// ---------------------------- Stage B --------------------------------------
static constexpr int TB = 32;
static constexpr int HB = 54;          // TB + 22 (halo 11 each side)
static constexpr int PB = 56;          // padded row
static constexpr int SB = HB * PB;     // 3024 floats per channel
static constexpr int WSTRIDE = 23 * 24;  // 552 floats per filter
static constexpr int SMEMB_FLOATS = 4 * SB + 4 * WSTRIDE;

extern __shared__ float smemB[];

__global__ __launch_bounds__(256)
void group_kernel(const float* __restrict__ Wg)
{
    float* sIn = smemB;            // 4 channels unpacked tile
    float* sW  = smemB + 4 * SB;   // 4 filters (23x23, rows padded to 24)

    const int bz  = blockIdx.z;    // b*4 + ori
    const int b   = bz >> 2;
    const int o   = bz & 3;
    const int x0  = blockIdx.x * TB;
    const int y0  = blockIdx.y * TB;
    const int tid = threadIdx.x;

    // Unpack this orientation's 4 channels from packed border into fp32 SMEM
    for (int idx = tid; idx < HB * HB; idx += 256) {
        int r = idx / HB, c = idx - r * HB;
        int gy = y0 - 11 + r, gx = x0 - 11 + c;
        uint32_t pk = 0;
        if ((unsigned)gy < IMG && (unsigned)gx < IMG)
            pk = g_border[((size_t)b * IMG + gy) * IMG + gx];
        uint32_t v = pk >> (8 * o);
        sIn[0 * SB + r * PB + c] = (float)( v       & 3u);
        sIn[1 * SB + r * PB + c] = (float)((v >> 2) & 3u);
        sIn[2 * SB + r * PB + c] = (float)((v >> 4) & 3u);
        sIn[3 * SB + r * PB + c] = (float)((v >> 6) & 3u);
    }
    for (int idx = tid; idx < 4 * 529; idx += 256) {
        int j   = idx / 529;
        int rem = idx - j * 529;
        int r = rem / 23, c = rem - r * 23;
        sW[j * WSTRIDE + r * 24 + c] = Wg[(size_t)(4 * o + j) * 529 + rem];
    }
    __syncthreads();

    const int tx  = tid & 7, ty = tid >> 3;
    const int x0l = tx * 4;

    int bitc[4];
#pragma unroll 1
    for (int cch = 0; cch < 4; cch++) {
        float acc[4] = {0.f, 0.f, 0.f, 0.f};
#pragma unroll 1
        for (int ky = 0; ky < 23; ky++) {
            float w[24], in[28];
            {
                const float4* s = (const float4*)&sW[cch * WSTRIDE + ky * 24];
#pragma unroll
                for (int i = 0; i < 6; i++) {
                    float4 v = s[i];
                    w[4*i] = v.x; w[4*i+1] = v.y; w[4*i+2] = v.z; w[4*i+3] = v.w;
                }
            }
            {
                const float4* s = (const float4*)&sIn[cch * SB + (ty + ky) * PB + x0l];
#pragma unroll
                for (int i = 0; i < 7; i++) {
                    float4 v = s[i];
                    in[4*i] = v.x; in[4*i+1] = v.y; in[4*i+2] = v.z; in[4*i+3] = v.w;
                }
            }
#pragma unroll
            for (int kx = 0; kx < 23; kx++) {
                float wv = w[kx];
#pragma unroll
                for (int p = 0; p < 4; p++)
                    acc[p] += in[kx + p] * wv;
            }
        }
        int bits = 0;
#pragma unroll
        for (int p = 0; p < 4; p++)
            if (acc[p] >= 1.f) bits |= 1 << p;
        bitc[cch] = bits;
    }

    const int gy = y0 + ty;
#pragma unroll
    for (int p = 0; p < 4; p++) {
        int b0 = (bitc[0] >> p) & 1;
        int b1 = (bitc[1] >> p) & 1;
        int b2 = (bitc[2] >> p) & 1;
        int b3 = (bitc[3] >> p) & 1;
        // spike(g0-g1)+spike(g2-g3) with g in {0,1}: b0&!b1 + b2&!b3
        int val = (b0 & (b1 ^ 1)) + (b2 & (b3 ^ 1));
        g_partial[(size_t)bz * NPIX + (size_t)gy * IMG + (x0 + x0l + p)]
            = (unsigned char)val;
    }
}

// ---------------------------- Stage C --------------------------------------
__global__ __launch_bounds__(256)
void combine_kernel(float* __restrict__ out)
{
    int idx = blockIdx.x * blockDim.x + threadIdx.x;
    if (idx >= NB * NPIX) return;
    int b = idx / NPIX;
    int i = idx - b * NPIX;
    const unsigned char* p = &g_partial[(size_t)b * 4 * NPIX + i];
    out[idx] = (float)((int)p[0] + (int)p[NPIX] + (int)p[2 * NPIX] + (int)p[3 * NPIX]);
}

// ---------------------------------------------------------------------------
extern "C" void kernel_launch(void* const* d_in, const int* in_sizes, int n_in,
                              void* d_out, int out_size)
{
    const float* inp = (const float*)d_in[0];   // (4,2,512,512)
    const float* Wb  = (const float*)d_in[1];   // (8,1,11,11)
    const float* Wg  = (const float*)d_in[2];   // (16,1,23,23)
    float* out = (float*)d_out;                 // (4,512,512)

    (void)in_sizes; (void)n_in; (void)out_size;

    cudaFuncSetAttribute(group_kernel,
                         cudaFuncAttributeMaxDynamicSharedMemorySize,
                         SMEMB_FLOATS * (int)sizeof(float));

    dim3 gA(IMG / TA, IMG / TA, NB);
    border_kernel<<<gA, 256>>>(inp, Wb);

    dim3 gB(IMG / TB, IMG / TB, NB * 4);
    group_kernel<<<gB, 256, SMEMB_FLOATS * sizeof(float)>>>(Wg);

    combine_kernel<<<(NB * NPIX + 255) / 256, 256>>>(out);
}

// round 7
// speedup vs baseline: 1.0918x; 1.0918x over previous
#include <cuda_runtime.h>
#include <cstdint>

// ---------------------------------------------------------------------------
// Border-ownership / grouping network, fused, with packed f32x2 FMA:
//   border: pos/neg channels share filters -> (inp0,inp1) in f32x2 lanes
//   group:  W_group = [g1,g1,g2,g2] per ori -> (c0,c1),(c2,c3) in f32x2 lanes
// Per-lane accumulation order identical to the scalar version -> bit-identical.
// ---------------------------------------------------------------------------

static constexpr int IMG  = 512;
static constexpr int NPIX = IMG * IMG;
static constexpr int NB   = 4;

__device__ uint32_t      g_border[(size_t)NB * NPIX];        // packed 16x2-bit
__device__ unsigned char g_partial[(size_t)NB * 4 * NPIX];   // per (b, ori)

typedef unsigned long long u64;

__device__ __forceinline__ u64 ffma2(u64 a, u64 b, u64 c) {
    u64 d;
    asm("fma.rn.f32x2 %0, %1, %2, %3;" : "=l"(d) : "l"(a), "l"(b), "l"(c));
    return d;
}
__device__ __forceinline__ float lo32f(u64 v) { return __uint_as_float((unsigned)v); }
__device__ __forceinline__ float hi32f(u64 v) { return __uint_as_float((unsigned)(v >> 32)); }
__device__ __forceinline__ u64 pack2(float a, float b) {
    return (u64)__float_as_uint(a) | ((u64)__float_as_uint(b) << 32);
}

// ---------------------------- Stage A: border ------------------------------
// Tile 32(x) x 64(y). Warp = 32 consecutive rows, 8 px per thread.
// SA=42 u64/row: lane stride 2*42=84 words == 20 (mod 32) -> all banks, no conflict.
static constexpr int TAX = 32, TAY = 64;
static constexpr int HAX = 42, HAY = 74, SA = 42;

__global__ __launch_bounds__(256, 1)
void border_kernel(const float* __restrict__ inp, const float* __restrict__ Wb)
{
    __shared__ __align__(16) u64 sP[HAY * SA];      // (ch0,ch1) pairs, 24.9 KB
    __shared__ __align__(16) u64 sW[8 * 11 * 12];   // splatted weights, 8.25 KB

    const int b   = blockIdx.z;
    const int x0  = blockIdx.x * TAX;
    const int y0  = blockIdx.y * TAY;
    const int tid = threadIdx.x;

    // Load both input channels as interleaved pairs (zero pad outside image)
    for (int idx = tid; idx < HAY * HAX; idx += 256) {
        int r = idx / HAX, c = idx - r * HAX;
        int gy = y0 - 5 + r, gx = x0 - 5 + c;
        float v0 = 0.f, v1 = 0.f;
        if ((unsigned)gy < IMG && (unsigned)gx < IMG) {
            size_t base = ((size_t)b * 2 * IMG + gy) * IMG + gx;
            v0 = inp[base];
            v1 = inp[base + (size_t)NPIX];
        }
        sP[r * SA + c] = pack2(v0, v1);
    }
    // Splat border weights (8 filters, 11x11), rows padded to 12 (pad = 0)
    for (int idx = tid; idx < 8 * 11 * 12; idx += 256) {
        int f = idx / 132, rem = idx - f * 132;
        int r = rem / 12, c = rem - r * 12;
        float w = (c < 11) ? Wb[(f * 11 + r) * 11 + c] : 0.f;
        sW[idx] = pack2(w, w);
    }
    __syncthreads();

    const int wrp  = tid >> 5, lane = tid & 31;
    const int tx   = wrp & 3, wy = wrp >> 2;
    const int row  = wy * 32 + lane;     // 0..63
    const int xb   = tx * 8;             // 8 px per thread

    unsigned pb[8], nb[8];
#pragma unroll
    for (int p = 0; p < 8; p++) { pb[p] = 0; nb[p] = 0; }

#pragma unroll 1
    for (int f = 0; f < 8; f++) {
        u64 acc[8];
#pragma unroll
        for (int p = 0; p < 8; p++) acc[p] = 0ull;
#pragma unroll 1
        for (int ky = 0; ky < 11; ky++) {
            u64 in[18];
            const u64* rp = &sP[(row + ky) * SA + xb];
#pragma unroll
            for (int i = 0; i < 9; i++) {
                ulonglong2 v = *(const ulonglong2*)(rp + 2 * i);
                in[2 * i] = v.x; in[2 * i + 1] = v.y;
            }
            const u64* wr = &sW[(f * 11 + ky) * 12];
#pragma unroll
            for (int kx = 0; kx < 11; kx++) {
                u64 wp = wr[kx];
#pragma unroll
                for (int p = 0; p < 8; p++)
                    acc[p] = ffma2(in[kx + p], wp, acc[p]);
            }
        }
#pragma unroll
        for (int p = 0; p < 8; p++) {
            if (lo32f(acc[p]) >= 1.f) pb[p] |= 1u << f;
            if (hi32f(acc[p]) >= 1.f) nb[p] |= 1u << f;
        }
    }

    // Per-pixel border logic: B_INH=1.5, G_INH=1.0 (identical to prior kernel)
    const int gy = y0 + row;
#pragma unroll
    for (int p = 0; p < 8; p++) {
        u64 cv = sP[(row + 5) * SA + xb + 5 + p];
        const float v = lo32f(cv) + hi32f(cv);
        int b13[4], b24[4];
#pragma unroll
        for (int o = 0; o < 4; o++) {
            float pe  = (float)((pb[p] >> (2 * o))     & 1u);
            float po  = (float)((pb[p] >> (2 * o + 1)) & 1u);
            float ne  = (float)((nb[p] >> (2 * o))     & 1u);
            float no_ = (float)((nb[p] >> (2 * o + 1)) & 1u);
            b13[o] = (v * (pe  - 1.5f * no_) >= 1.f ? 1 : 0)
                   + (v * (ne  - 1.5f * po ) >= 1.f ? 1 : 0);
            b24[o] = (v * (po  - 1.5f * ne ) >= 1.f ? 1 : 0)
                   + (v * (no_ - 1.5f * pe ) >= 1.f ? 1 : 0);
        }
        int m = 0;
#pragma unroll
        for (int o = 0; o < 4; o++) {
            int d = b13[o] - b24[o];
            int t = d < 0 ? -d : d;
            m = t > m ? t : m;
        }
        uint32_t pk = 0;
#pragma unroll
        for (int o = 0; o < 4; o++) {
            int d   = b13[o] - b24[o];
            int t   = d < 0 ? -d : d;
            int wta = (t == m);
            int b1p = wta && (d >= 1);
            int b1n = wta && (d <= -1);
            int c0 = b1p ? b13[o] : 0;
            int c1 = b1p ? b24[o] : 0;
            int c2 = b1n ? b24[o] : 0;
            int c3 = b1n ? b13[o] : 0;
            pk |= (uint32_t)(c0 | (c1 << 2) | (c2 << 4) | (c3 << 6)) << (8 * o);
        }
        g_border[((size_t)b * IMG + gy) * IMG + (x0 + xb + p)] = pk;
    }
}

// ---------------------------- Stage B: group -------------------------------
// Tile 32(x) x 64(y). SB=54 u64/row: lane stride 108 words == 12 (mod 32)
// -> all 32 banks covered, conflict-free LDS.128.
static constexpr int TBX = 32, TBY = 64;
static constexpr int HBX = 54, HBY = 86, SBu = 54;
static constexpr int WS  = 23 * 24;                       // splat u64 per filter
static constexpr int GSMEM_U64 = 2 * HBY * SBu + 2 * WS;  // 10392 u64 = 83.1 KB

extern __shared__ u64 gsm[];

__global__ __launch_bounds__(256, 1)
void group_kernel(const float* __restrict__ Wg)
{
    u64* p0  = gsm;                    // (c0,c1) pairs
    u64* p1  = gsm + HBY * SBu;        // (c2,c3) pairs
    u64* wsp = gsm + 2 * HBY * SBu;    // 2 splatted filters (g1, g2)

    const int bz  = blockIdx.z;        // b*4 + ori
    const int b   = bz >> 2;
    const int o   = bz & 3;
    const int x0  = blockIdx.x * TBX;
    const int y0  = blockIdx.y * TBY;
    const int tid = threadIdx.x;

    // Unpack packed border into channel-pair planes
    for (int idx = tid; idx < HBY * HBX; idx += 256) {
        int r = idx / HBX, c = idx - r * HBX;
        int gy = y0 - 11 + r, gx = x0 - 11 + c;
        uint32_t pk = 0;
        if ((unsigned)gy < IMG && (unsigned)gx < IMG)
            pk = g_border[((size_t)b * IMG + gy) * IMG + gx];
        uint32_t v = pk >> (8 * o);
        p0[r * SBu + c] = pack2((float)( v       & 3u), (float)((v >> 2) & 3u));
        p1[r * SBu + c] = pack2((float)((v >> 4) & 3u), (float)((v >> 6) & 3u));
    }
    // Splat weights: plane0 uses filter 4o+0 (== 4o+1), plane1 uses 4o+2 (== 4o+3)
    for (int idx = tid; idx < 2 * WS; idx += 256) {
        int j = idx / WS, rem = idx - j * WS;
        int r = rem / 24, c = rem - r * 24;
        float w = (c < 23) ? Wg[(size_t)(4 * o + 2 * j) * 529 + r * 23 + c] : 0.f;
        wsp[idx] = pack2(w, w);
    }
    __syncthreads();

    const int wrp  = tid >> 5, lane = tid & 31;
    const int tx   = wrp & 3, wy = wrp >> 2;
    const int row  = wy * 32 + lane;
    const int xb   = tx * 8;

    unsigned bitsA[2], bitsB[2];
#pragma unroll 1
    for (int pl = 0; pl < 2; pl++) {
        const u64* plane = pl ? p1 : p0;
        const u64* wf    = wsp + pl * WS;
        u64 acc[8];
#pragma unroll
        for (int p = 0; p < 8; p++) acc[p] = 0ull;
#pragma unroll 1
        for (int ky = 0; ky < 23; ky++) {
            u64 in[30];
            const u64* rp = &plane[(row + ky) * SBu + xb];
#pragma unroll
            for (int i = 0; i < 15; i++) {
                ulonglong2 v = *(const ulonglong2*)(rp + 2 * i);
                in[2 * i] = v.x; in[2 * i + 1] = v.y;
            }
            const u64* wr = wf + ky * 24;
#pragma unroll
            for (int kx = 0; kx < 23; kx++) {
                u64 wp = wr[kx];
#pragma unroll
                for (int p = 0; p < 8; p++)
                    acc[p] = ffma2(in[kx + p], wp, acc[p]);
            }
        }
        unsigned a = 0, bb = 0;
#pragma unroll
        for (int p = 0; p < 8; p++) {
            if (lo32f(acc[p]) >= 1.f) a  |= 1u << p;
            if (hi32f(acc[p]) >= 1.f) bb |= 1u << p;
        }
        bitsA[pl] = a; bitsB[pl] = bb;
    }

    const int gy = y0 + row;
#pragma unroll
    for (int p = 0; p < 8; p++) {
        int g0 = (bitsA[0] >> p) & 1;
        int g1 = (bitsB[0] >> p) & 1;
        int g2 = (bitsA[1] >> p) & 1;
        int g3 = (bitsB[1] >> p) & 1;
        int val = (g0 & (g1 ^ 1)) + (g2 & (g3 ^ 1));
        g_partial[(size_t)bz * NPIX + (size_t)gy * IMG + (x0 + xb + p)]
            = (unsigned char)val;
    }
}

// ---------------------------- Stage C: combine -----------------------------
__global__ __launch_bounds__(256)
void combine_kernel(float* __restrict__ out)
{
    int idx = blockIdx.x * blockDim.x + threadIdx.x;
    if (idx >= NB * NPIX) return;
    int b = idx / NPIX;
    int i = idx - b * NPIX;
    const unsigned char* p = &g_partial[(size_t)b * 4 * NPIX + i];
    out[idx] = (float)((int)p[0] + (int)p[NPIX] + (int)p[2 * NPIX] + (int)p[3 * NPIX]);
}

// ---------------------------------------------------------------------------
extern "C" void kernel_launch(void* const* d_in, const int* in_sizes, int n_in,
                              void* d_out, int out_size)
{
    const float* inp = (const float*)d_in[0];   // (4,2,512,512)
    const float* Wb  = (const float*)d_in[1];   // (8,1,11,11)
    const float* Wg  = (const float*)d_in[2];   // (16,1,23,23)
    float* out = (float*)d_out;                 // (4,512,512)

    (void)in_sizes; (void)n_in; (void)out_size;

    cudaFuncSetAttribute(group_kernel,
                         cudaFuncAttributeMaxDynamicSharedMemorySize,
                         GSMEM_U64 * (int)sizeof(u64));

    dim3 gA(IMG / TAX, IMG / TAY, NB);
    border_kernel<<<gA, 256>>>(inp, Wb);

    dim3 gB(IMG / TBX, IMG / TBY, NB * 4);
    group_kernel<<<gB, 256, GSMEM_U64 * sizeof(u64)>>>(Wg);

    combine_kernel<<<(NB * NPIX + 255) / 256, 256>>>(out);
}